// round 5
// baseline (speedup 1.0000x reference)
#include <cuda_runtime.h>
#include <math_constants.h>

// Regular (3,6) LDPC neural offset min-sum decoder.
// N_VAR=524288, DV=3 -> edges of var v are exactly {3v, 3v+1, 3v+2} (edge_var is
// repeat(arange,3)), so the variable side needs NO indirection. Only the check
// side (edge_chk = random permutation) requires gather/scatter.
//
// Storage is edge-major (variable-major). Per iteration:
//   check kernel: gather 6 v2c (random 4B), two-min + sign product, scatter c2v.
//   var kernel:   fully coalesced; v2c_new[e] = (llr[v] + sum c2v) - c2v[e].
// Tie semantics: reference's first-index argmin + min2 is value-equivalent to
// plain two-smallest tracking (ties => min2==min1 => raw identical on all edges),
// so the atomic-order-nondeterministic check edge table yields deterministic output.

#define NVAR  524288
#define NCHK  262144
#define NEDGE 1572864
#define DCC   6

static __device__ float g_v2c[NEDGE];
static __device__ float g_c2v[NEDGE];
static __device__ int   g_ce[NEDGE];    // check-major list of edge ids
static __device__ int   g_cnt[NCHK];    // per-check fill counters

__global__ void k_init(const float* __restrict__ llr) {
    int e = blockIdx.x * blockDim.x + threadIdx.x;
    if (e < NCHK) g_cnt[e] = 0;
    if (e < NEDGE) g_v2c[e] = llr[e / 3];
}

__global__ void k_build(const int* __restrict__ edge_chk) {
    int e = blockIdx.x * blockDim.x + threadIdx.x;
    if (e < NEDGE) {
        int c = edge_chk[e];
        int s = atomicAdd(&g_cnt[c], 1);
        g_ce[c * DCC + s] = e;
    }
}

__global__ void k_check(const float* __restrict__ beta,
                        const float* __restrict__ alpha, int t) {
    int c = blockIdx.x * blockDim.x + threadIdx.x;
    if (c >= NCHK) return;

    int e[DCC];
    float v[DCC];
#pragma unroll
    for (int s = 0; s < DCC; s++) e[s] = g_ce[c * DCC + s];
#pragma unroll
    for (int s = 0; s < DCC; s++) v[s] = g_v2c[e[s]];   // random gather (L2)

    float m1 = CUDART_INF_F, m2 = CUDART_INF_F, sp = 1.0f;
    int   as = 0;
    float sg[DCC];
#pragma unroll
    for (int s = 0; s < DCC; s++) {
        float x = v[s];
        float g = (x > 0.0f) ? 1.0f : ((x < 0.0f) ? -1.0f : 0.0f); // jnp.sign
        sg[s] = g;
        sp *= g;
        float m = fabsf(x);
        if (m < m1) { m2 = m1; m1 = m; as = s; }
        else if (m < m2) { m2 = m; }
    }

    float b = __ldg(&beta[t]);
    float a = __ldg(&alpha[t]);
    float r1 = fmaxf(m1 - b, 0.0f) - a;
    float r2 = fmaxf(m2 - b, 0.0f) - a;

#pragma unroll
    for (int s = 0; s < DCC; s++) {
        float val = (s == as) ? r2 : r1;
        g_c2v[e[s]] = sp * sg[s] * val;                  // random scatter (L2)
    }
}

__global__ void k_var(const float* __restrict__ llr) {
    int v = blockIdx.x * blockDim.x + threadIdx.x;
    if (v >= NVAR) return;
    float c0 = g_c2v[3 * v + 0];
    float c1 = g_c2v[3 * v + 1];
    float c2 = g_c2v[3 * v + 2];
    float p  = llr[v] + (c0 + c1 + c2);
    g_v2c[3 * v + 0] = p - c0;
    g_v2c[3 * v + 1] = p - c1;
    g_v2c[3 * v + 2] = p - c2;
}

// Final variable update: posterior + hard decision.
// Layout: out[0..NVAR) = decoded bits (as float 0/1), out[NVAR..2NVAR) = posterior.
__global__ void k_final_f(const float* __restrict__ llr, float* __restrict__ out) {
    int v = blockIdx.x * blockDim.x + threadIdx.x;
    if (v >= NVAR) return;
    float c0 = g_c2v[3 * v + 0];
    float c1 = g_c2v[3 * v + 1];
    float c2 = g_c2v[3 * v + 2];
    float p  = llr[v] + (c0 + c1 + c2);
    out[v]        = (p < 0.0f) ? 1.0f : 0.0f;
    out[NVAR + v] = p;
}

__global__ void k_final_i(const float* __restrict__ llr, int* __restrict__ out) {
    int v = blockIdx.x * blockDim.x + threadIdx.x;
    if (v >= NVAR) return;
    float c0 = g_c2v[3 * v + 0];
    float c1 = g_c2v[3 * v + 1];
    float c2 = g_c2v[3 * v + 2];
    float p  = llr[v] + (c0 + c1 + c2);
    out[v] = (p < 0.0f) ? 1 : 0;
}

extern "C" void kernel_launch(void* const* d_in, const int* in_sizes, int n_in,
                              void* d_out, int out_size) {
    const float* llr      = (const float*)d_in[0];
    const float* beta     = (const float*)d_in[1];
    const float* alpha    = (const float*)d_in[2];
    // d_in[3] = edge_var (implicit: e/3, unused), d_in[4] = edge_chk
    const int*   edge_chk = (const int*)d_in[4];
    const int T = in_sizes[1];   // number of iterations (10)

    const int TB = 256;
    const int gE = (NEDGE + TB - 1) / TB;
    const int gC = (NCHK  + TB - 1) / TB;
    const int gV = (NVAR  + TB - 1) / TB;

    k_init <<<gE, TB>>>(llr);
    k_build<<<gE, TB>>>(edge_chk);

    for (int t = 0; t < T; t++) {
        k_check<<<gC, TB>>>(beta, alpha, t);
        if (t < T - 1) k_var<<<gV, TB>>>(llr);
    }

    if (out_size >= 2 * NVAR) {
        k_final_f<<<gV, TB>>>(llr, (float*)d_out);
    } else {
        k_final_i<<<gV, TB>>>(llr, (int*)d_out);
    }
}